// round 1
// baseline (speedup 1.0000x reference)
#include <cuda_runtime.h>
#include <math.h>

#define N_NODES 8192
#define K_NB    32
#define D_DIM   128
#define H_DIM   256

// Scratch (allocation-free rule: __device__ globals)
__device__ float g_P[N_NODES * H_DIM];   // x @ W1[:128] + b1
__device__ float g_Q[N_NODES * H_DIM];   // x @ W1[128:]

// ---------------------------------------------------------------------------
// Zero the whole output buffer (Y_pred + pairwise), float4 stores.
// total elements = 8192 + 8192*8192 = 67117056 (divisible by 4)
// ---------------------------------------------------------------------------
__global__ void zero_kernel(float4* __restrict__ out, int n4) {
    int stride = gridDim.x * blockDim.x;
    float4 z = make_float4(0.f, 0.f, 0.f, 0.f);
    for (int i = blockIdx.x * blockDim.x + threadIdx.x; i < n4; i += stride)
        out[i] = z;
}

// ---------------------------------------------------------------------------
// PQ precompute: per block, 16 rows of x; thread t owns output column t.
// P[r][t] = b1[t] + sum_d x[r][d] * W1[d][t]
// Q[r][t] =          sum_d x[r][d] * W1[128+d][t]
// ---------------------------------------------------------------------------
#define ROWS_PER_BLK 16
__global__ __launch_bounds__(256) void pq_kernel(
    const float* __restrict__ x, const float* __restrict__ W1,
    const float* __restrict__ b1)
{
    __shared__ float xs[ROWS_PER_BLK * D_DIM];
    const int t = threadIdx.x;
    const int row0 = blockIdx.x * ROWS_PER_BLK;

    // stage 16x128 floats of x
    const float4* xsrc = (const float4*)(x + (size_t)row0 * D_DIM);
    float4* xdst = (float4*)xs;
    #pragma unroll
    for (int i = 0; i < (ROWS_PER_BLK * D_DIM / 4) / 256; i++)
        xdst[t + i * 256] = xsrc[t + i * 256];
    __syncthreads();

    float accP[ROWS_PER_BLK], accQ[ROWS_PER_BLK];
    #pragma unroll
    for (int r = 0; r < ROWS_PER_BLK; r++) { accP[r] = 0.f; accQ[r] = 0.f; }

    #pragma unroll 4
    for (int d = 0; d < D_DIM; d++) {
        float wp = W1[d * H_DIM + t];
        float wq = W1[(D_DIM + d) * H_DIM + t];
        #pragma unroll
        for (int r = 0; r < ROWS_PER_BLK; r++) {
            float xv = xs[r * D_DIM + d];
            accP[r] = fmaf(xv, wp, accP[r]);
            accQ[r] = fmaf(xv, wq, accQ[r]);
        }
    }
    float bb = b1[t];
    #pragma unroll
    for (int r = 0; r < ROWS_PER_BLK; r++) {
        g_P[(size_t)(row0 + r) * H_DIM + t] = accP[r] + bb;
        g_Q[(size_t)(row0 + r) * H_DIM + t] = accQ[r];
    }
}

// ---------------------------------------------------------------------------
// Main kernel: one block per node i (8192 blocks, 256 threads).
// h1[j][k] = relu(P[i][k] + Q[cj][k])           -> smem [k][j]
// h2[j][t] = relu(b2[t] + sum_k h1[j][k]*W2[k][t])   (thread t, acc[32])
// mlp[j]   = b3 + sum_t h2[j][t]*W3[t]          (warp+block reduce)
// scores   = softmax_j(b*|mlp|), w = mlp*scores
// Y_pred[i] = sum_j (t[cj]-e_hat[cj]) * w[j]
// pairwise[i][cj] = w[j] (serial, last-wins), pairwise[i][i] = 0
// ---------------------------------------------------------------------------
__global__ __launch_bounds__(256) void mlp_kernel(
    const int* __restrict__ nbrs,
    const float* __restrict__ t_arr, const float* __restrict__ e_hat,
    const float* __restrict__ W2, const float* __restrict__ b2,
    const float* __restrict__ W3, const float* __restrict__ b3,
    const float* __restrict__ b_scal,
    float* __restrict__ ypred, float* __restrict__ pairwise)
{
    __shared__ float h1s[H_DIM * K_NB];   // [k][j], 32 KB
    __shared__ float red[8][K_NB];        // per-warp partials
    __shared__ int   cjs[K_NB];

    const int tid  = threadIdx.x;
    const int i    = blockIdx.x;
    const int lane = tid & 31;
    const int warp = tid >> 5;

    if (tid < K_NB) cjs[tid] = nbrs[i * (K_NB + 1) + 1 + tid];
    __syncthreads();

    // layer 1: thread tid owns hidden unit 'tid'
    {
        float p = g_P[(size_t)i * H_DIM + tid];
        #pragma unroll 8
        for (int j = 0; j < K_NB; j++) {
            int cj = cjs[j];
            float v = p + g_Q[(size_t)cj * H_DIM + tid];
            h1s[tid * K_NB + j] = fmaxf(v, 0.f);
        }
    }
    __syncthreads();

    // layer 2: acc[j] = sum_k h1[j][k] * W2[k][tid]
    float acc[K_NB];
    #pragma unroll
    for (int j = 0; j < K_NB; j++) acc[j] = 0.f;

    const float4* h1v = (const float4*)h1s;   // index: k*8 + j/4
    #pragma unroll 2
    for (int k = 0; k < H_DIM; k += 4) {
        float w0 = W2[(k + 0) * H_DIM + tid];
        float w1 = W2[(k + 1) * H_DIM + tid];
        float w2 = W2[(k + 2) * H_DIM + tid];
        float w3 = W2[(k + 3) * H_DIM + tid];
        #pragma unroll
        for (int jg = 0; jg < K_NB / 4; jg++) {
            float4 a0 = h1v[(k + 0) * 8 + jg];
            float4 a1 = h1v[(k + 1) * 8 + jg];
            float4 a2 = h1v[(k + 2) * 8 + jg];
            float4 a3 = h1v[(k + 3) * 8 + jg];
            acc[4 * jg + 0] = fmaf(a0.x, w0, fmaf(a1.x, w1, fmaf(a2.x, w2, fmaf(a3.x, w3, acc[4 * jg + 0]))));
            acc[4 * jg + 1] = fmaf(a0.y, w0, fmaf(a1.y, w1, fmaf(a2.y, w2, fmaf(a3.y, w3, acc[4 * jg + 1]))));
            acc[4 * jg + 2] = fmaf(a0.z, w0, fmaf(a1.z, w1, fmaf(a2.z, w2, fmaf(a3.z, w3, acc[4 * jg + 2]))));
            acc[4 * jg + 3] = fmaf(a0.w, w0, fmaf(a1.w, w1, fmaf(a2.w, w2, fmaf(a3.w, w3, acc[4 * jg + 3]))));
        }
    }

    // layer 3 partial + block reduce over the 256 hidden units
    {
        float b2t = b2[tid];
        float w3t = W3[tid];
        #pragma unroll
        for (int j = 0; j < K_NB; j++) {
            float v = fmaxf(acc[j] + b2t, 0.f) * w3t;
            #pragma unroll
            for (int o = 16; o > 0; o >>= 1)
                v += __shfl_xor_sync(0xffffffffu, v, o);
            if (lane == 0) red[warp][j] = v;
        }
    }
    __syncthreads();

    if (warp == 0) {
        const int j = lane;
        float mlp = b3[0];
        #pragma unroll
        for (int w = 0; w < 8; w++) mlp += red[w][j];

        // softmax over j of b*|mlp|
        float a = b_scal[0] * fabsf(mlp);
        float amax = a;
        #pragma unroll
        for (int o = 16; o > 0; o >>= 1)
            amax = fmaxf(amax, __shfl_xor_sync(0xffffffffu, amax, o));
        float e = __expf(a - amax);
        float esum = e;
        #pragma unroll
        for (int o = 16; o > 0; o >>= 1)
            esum += __shfl_xor_sync(0xffffffffu, esum, o);
        float wgt = mlp * (e / esum);

        int cj = cjs[j];
        float prop = t_arr[cj] - e_hat[cj];
        float yp = prop * wgt;
        #pragma unroll
        for (int o = 16; o > 0; o >>= 1)
            yp += __shfl_xor_sync(0xffffffffu, yp, o);
        if (lane == 0) ypred[i] = yp;

        // serial scatter (ascending j, last write wins) from lane 0
        float* prow = pairwise + (size_t)i * N_NODES;
        #pragma unroll
        for (int jj = 0; jj < K_NB; jj++) {
            float wj = __shfl_sync(0xffffffffu, wgt, jj);
            int  cjj = __shfl_sync(0xffffffffu, cj,  jj);
            if (lane == 0) prow[cjj] = wj;
        }
        if (lane == 0) prow[i] = 0.f;
    }
}

// ---------------------------------------------------------------------------
extern "C" void kernel_launch(void* const* d_in, const int* in_sizes, int n_in,
                              void* d_out, int out_size) {
    const float* x     = (const float*)d_in[0];
    const int*   nbrs  = (const int*)  d_in[1];
    const float* t_arr = (const float*)d_in[2];
    const float* e_hat = (const float*)d_in[3];
    const float* W1    = (const float*)d_in[4];
    const float* b1    = (const float*)d_in[5];
    const float* W2    = (const float*)d_in[6];
    const float* b2    = (const float*)d_in[7];
    const float* W3    = (const float*)d_in[8];
    const float* b3    = (const float*)d_in[9];
    const float* bsc   = (const float*)d_in[10];

    float* ypred    = (float*)d_out;
    float* pairwise = ypred + N_NODES;

    int n4 = out_size / 4;
    zero_kernel<<<4096, 256>>>((float4*)d_out, n4);
    pq_kernel<<<N_NODES / ROWS_PER_BLK, 256>>>(x, W1, b1);
    mlp_kernel<<<N_NODES, 256>>>(nbrs, t_arr, e_hat, W2, b2, W3, b3, bsc,
                                 ypred, pairwise);
}

// round 2
// speedup vs baseline: 1.0073x; 1.0073x over previous
#include <cuda_runtime.h>
#include <math.h>

#define N_NODES 8192
#define K_NB    32
#define D_DIM   128
#define H_DIM   256

typedef unsigned long long u64;

__device__ float g_P[N_NODES * H_DIM];   // x @ W1[:128] + b1
__device__ float g_Q[N_NODES * H_DIM];   // x @ W1[128:]

__device__ __forceinline__ u64 pack2(float v) {
    u64 r; asm("mov.b64 %0, {%1, %1};" : "=l"(r) : "f"(v)); return r;
}
__device__ __forceinline__ u64 ffma2(u64 a, u64 b, u64 c) {
    u64 d; asm("fma.rn.f32x2 %0, %1, %2, %3;" : "=l"(d) : "l"(a), "l"(b), "l"(c));
    return d;
}
__device__ __forceinline__ void unpack2(u64 v, float& lo, float& hi) {
    asm("mov.b64 {%0, %1}, %2;" : "=f"(lo), "=f"(hi) : "l"(v));
}

// ---------------------------------------------------------------------------
__global__ void zero_kernel(float4* __restrict__ out, int n4) {
    int stride = gridDim.x * blockDim.x;
    float4 z = make_float4(0.f, 0.f, 0.f, 0.f);
    for (int i = blockIdx.x * blockDim.x + threadIdx.x; i < n4; i += stride)
        out[i] = z;
}

// ---------------------------------------------------------------------------
#define ROWS_PER_BLK 16
__global__ __launch_bounds__(256) void pq_kernel(
    const float* __restrict__ x, const float* __restrict__ W1,
    const float* __restrict__ b1)
{
    __shared__ float xs[ROWS_PER_BLK * D_DIM];
    const int t = threadIdx.x;
    const int row0 = blockIdx.x * ROWS_PER_BLK;

    const float4* xsrc = (const float4*)(x + (size_t)row0 * D_DIM);
    float4* xdst = (float4*)xs;
    #pragma unroll
    for (int i = 0; i < (ROWS_PER_BLK * D_DIM / 4) / 256; i++)
        xdst[t + i * 256] = xsrc[t + i * 256];
    __syncthreads();

    float accP[ROWS_PER_BLK], accQ[ROWS_PER_BLK];
    #pragma unroll
    for (int r = 0; r < ROWS_PER_BLK; r++) { accP[r] = 0.f; accQ[r] = 0.f; }

    #pragma unroll 4
    for (int d = 0; d < D_DIM; d++) {
        float wp = W1[d * H_DIM + t];
        float wq = W1[(D_DIM + d) * H_DIM + t];
        #pragma unroll
        for (int r = 0; r < ROWS_PER_BLK; r++) {
            float xv = xs[r * D_DIM + d];
            accP[r] = fmaf(xv, wp, accP[r]);
            accQ[r] = fmaf(xv, wq, accQ[r]);
        }
    }
    float bb = b1[t];
    #pragma unroll
    for (int r = 0; r < ROWS_PER_BLK; r++) {
        g_P[(size_t)(row0 + r) * H_DIM + t] = accP[r] + bb;
        g_Q[(size_t)(row0 + r) * H_DIM + t] = accQ[r];
    }
}

// ---------------------------------------------------------------------------
// Main kernel: one block per node i (8192 blocks, 256 threads).
// Layer 2 uses packed fp32x2 FMA (FFMA2) over paired j lanes.
// ---------------------------------------------------------------------------
__global__ __launch_bounds__(256) void mlp_kernel(
    const int* __restrict__ nbrs,
    const float* __restrict__ t_arr, const float* __restrict__ e_hat,
    const float* __restrict__ W2, const float* __restrict__ b2,
    const float* __restrict__ W3, const float* __restrict__ b3,
    const float* __restrict__ b_scal,
    float* __restrict__ ypred, float* __restrict__ pairwise)
{
    __shared__ float h1s[H_DIM * K_NB];   // [k][j], 32 KB
    __shared__ float red[8][K_NB];
    __shared__ int   cjs[K_NB];

    const int tid  = threadIdx.x;
    const int i    = blockIdx.x;
    const int lane = tid & 31;
    const int warp = tid >> 5;

    if (tid < K_NB) cjs[tid] = nbrs[i * (K_NB + 1) + 1 + tid];
    __syncthreads();

    // layer 1: thread tid owns hidden unit 'tid'
    {
        float p = g_P[(size_t)i * H_DIM + tid];
        #pragma unroll 8
        for (int j = 0; j < K_NB; j++) {
            int cj = cjs[j];
            float v = p + g_Q[(size_t)cj * H_DIM + tid];
            h1s[tid * K_NB + j] = fmaxf(v, 0.f);
        }
    }
    __syncthreads();

    // layer 2 (packed): acc2[p] covers a pair of adjacent j.
    // pair mapping: h1v[k*8+q].x = (j=4q, 4q+1), .y = (j=4q+2, 4q+3)
    u64 acc2[K_NB / 2];
    #pragma unroll
    for (int p = 0; p < K_NB / 2; p++) acc2[p] = 0ull;

    const ulonglong2* h1v = (const ulonglong2*)h1s;
    #pragma unroll 4
    for (int k = 0; k < H_DIM; k++) {
        u64 wp = pack2(W2[k * H_DIM + tid]);
        #pragma unroll
        for (int q = 0; q < 8; q++) {
            ulonglong2 a = h1v[k * 8 + q];
            acc2[2 * q + 0] = ffma2(a.x, wp, acc2[2 * q + 0]);
            acc2[2 * q + 1] = ffma2(a.y, wp, acc2[2 * q + 1]);
        }
    }

    float acc[K_NB];
    #pragma unroll
    for (int q = 0; q < 8; q++) {
        unpack2(acc2[2 * q + 0], acc[4 * q + 0], acc[4 * q + 1]);
        unpack2(acc2[2 * q + 1], acc[4 * q + 2], acc[4 * q + 3]);
    }

    // layer 3 partial + block reduce over the 256 hidden units
    {
        float b2t = b2[tid];
        float w3t = W3[tid];
        #pragma unroll
        for (int j = 0; j < K_NB; j++) {
            float v = fmaxf(acc[j] + b2t, 0.f) * w3t;
            #pragma unroll
            for (int o = 16; o > 0; o >>= 1)
                v += __shfl_xor_sync(0xffffffffu, v, o);
            if (lane == 0) red[warp][j] = v;
        }
    }
    __syncthreads();

    if (warp == 0) {
        const int j = lane;
        float mlp = b3[0];
        #pragma unroll
        for (int w = 0; w < 8; w++) mlp += red[w][j];

        float a = b_scal[0] * fabsf(mlp);
        float amax = a;
        #pragma unroll
        for (int o = 16; o > 0; o >>= 1)
            amax = fmaxf(amax, __shfl_xor_sync(0xffffffffu, amax, o));
        float e = __expf(a - amax);
        float esum = e;
        #pragma unroll
        for (int o = 16; o > 0; o >>= 1)
            esum += __shfl_xor_sync(0xffffffffu, esum, o);
        float wgt = mlp * (e / esum);

        int cj = cjs[j];
        float prop = t_arr[cj] - e_hat[cj];
        float yp = prop * wgt;
        #pragma unroll
        for (int o = 16; o > 0; o >>= 1)
            yp += __shfl_xor_sync(0xffffffffu, yp, o);
        if (lane == 0) ypred[i] = yp;

        // serial scatter (ascending j, last write wins)
        float* prow = pairwise + (size_t)i * N_NODES;
        #pragma unroll
        for (int jj = 0; jj < K_NB; jj++) {
            float wj = __shfl_sync(0xffffffffu, wgt, jj);
            int  cjj = __shfl_sync(0xffffffffu, cj,  jj);
            if (lane == 0) prow[cjj] = wj;
        }
        if (lane == 0) prow[i] = 0.f;
    }
}

// ---------------------------------------------------------------------------
extern "C" void kernel_launch(void* const* d_in, const int* in_sizes, int n_in,
                              void* d_out, int out_size) {
    const float* x     = (const float*)d_in[0];
    const int*   nbrs  = (const int*)  d_in[1];
    const float* t_arr = (const float*)d_in[2];
    const float* e_hat = (const float*)d_in[3];
    const float* W1    = (const float*)d_in[4];
    const float* b1    = (const float*)d_in[5];
    const float* W2    = (const float*)d_in[6];
    const float* b2    = (const float*)d_in[7];
    const float* W3    = (const float*)d_in[8];
    const float* b3    = (const float*)d_in[9];
    const float* bsc   = (const float*)d_in[10];

    float* ypred    = (float*)d_out;
    float* pairwise = ypred + N_NODES;

    int n4 = out_size / 4;
    zero_kernel<<<4096, 256>>>((float4*)d_out, n4);
    pq_kernel<<<N_NODES / ROWS_PER_BLK, 256>>>(x, W1, b1);
    mlp_kernel<<<N_NODES, 256>>>(nbrs, t_arr, e_hat, W2, b2, W3, b3, bsc,
                                 ypred, pairwise);
}

// round 4
// speedup vs baseline: 1.1036x; 1.0956x over previous
#include <cuda_runtime.h>
#include <cstdint>
#include <stdint.h>
#include <math.h>

#define N_NODES 8192
#define K_NB    32
#define D_DIM   128
#define H_DIM   256
#define KC      32
#define NTILES  (H_DIM / KC)   // 8

typedef unsigned long long u64;
typedef unsigned int       u32;

__device__ float g_P[N_NODES * H_DIM];   // x @ W1[:128] + b1
__device__ float g_Q[N_NODES * H_DIM];   // x @ W1[128:]

__device__ __forceinline__ u64 pack2(float v) {
    u64 r; asm("mov.b64 %0, {%1, %1};" : "=l"(r) : "f"(v)); return r;
}
__device__ __forceinline__ u64 ffma2(u64 a, u64 b, u64 c) {
    u64 d; asm("fma.rn.f32x2 %0, %1, %2, %3;" : "=l"(d) : "l"(a), "l"(b), "l"(c));
    return d;
}
__device__ __forceinline__ void unpack2(u64 v, float& lo, float& hi) {
    asm("mov.b64 {%0, %1}, %2;" : "=f"(lo), "=f"(hi) : "l"(v));
}
__device__ __forceinline__ void cp_async16(u32 saddr, const void* gaddr) {
    asm volatile("cp.async.cg.shared.global [%0], [%1], 16;"
                 :: "r"(saddr), "l"(gaddr));
}
__device__ __forceinline__ void cp_commit() {
    asm volatile("cp.async.commit_group;");
}
template <int N>
__device__ __forceinline__ void cp_wait() {
    asm volatile("cp.async.wait_group %0;" :: "n"(N));
}

// ---------------------------------------------------------------------------
__global__ void zero_kernel(float4* __restrict__ out, int n4) {
    int stride = gridDim.x * blockDim.x;
    float4 z = make_float4(0.f, 0.f, 0.f, 0.f);
    for (int i = blockIdx.x * blockDim.x + threadIdx.x; i < n4; i += stride)
        out[i] = z;
}

// ---------------------------------------------------------------------------
#define ROWS_PER_BLK 16
__global__ __launch_bounds__(256) void pq_kernel(
    const float* __restrict__ x, const float* __restrict__ W1,
    const float* __restrict__ b1)
{
    __shared__ float xs[ROWS_PER_BLK * D_DIM];
    const int t = threadIdx.x;
    const int row0 = blockIdx.x * ROWS_PER_BLK;

    const float4* xsrc = (const float4*)(x + (size_t)row0 * D_DIM);
    float4* xdst = (float4*)xs;
    #pragma unroll
    for (int i = 0; i < (ROWS_PER_BLK * D_DIM / 4) / 256; i++)
        xdst[t + i * 256] = xsrc[t + i * 256];
    __syncthreads();

    float accP[ROWS_PER_BLK], accQ[ROWS_PER_BLK];
    #pragma unroll
    for (int r = 0; r < ROWS_PER_BLK; r++) { accP[r] = 0.f; accQ[r] = 0.f; }

    #pragma unroll 4
    for (int d = 0; d < D_DIM; d++) {
        float wp = W1[d * H_DIM + t];
        float wq = W1[(D_DIM + d) * H_DIM + t];
        #pragma unroll
        for (int r = 0; r < ROWS_PER_BLK; r++) {
            float xv = xs[r * D_DIM + d];
            accP[r] = fmaf(xv, wp, accP[r]);
            accQ[r] = fmaf(xv, wq, accQ[r]);
        }
    }
    float bb = b1[t];
    #pragma unroll
    for (int r = 0; r < ROWS_PER_BLK; r++) {
        g_P[(size_t)(row0 + r) * H_DIM + t] = accP[r] + bb;
        g_Q[(size_t)(row0 + r) * H_DIM + t] = accQ[r];
    }
}

// ---------------------------------------------------------------------------
// Main kernel: one block per node i. Dynamic smem layout:
//   W2s[2][KC*H]  (64 KB, double-buffered k-tiles of W2 via cp.async)
//   h1s[H][K_NB]  (32 KB, k-major, conflict-free stores)
//   red[8*K_NB], cjs[K_NB]
// ---------------------------------------------------------------------------
#define SMEM_FLOATS (2 * KC * H_DIM + H_DIM * K_NB + 8 * K_NB + K_NB)
#define SMEM_BYTES  (SMEM_FLOATS * 4)

__global__ __launch_bounds__(256) void mlp_kernel(
    const int* __restrict__ nbrs,
    const float* __restrict__ t_arr, const float* __restrict__ e_hat,
    const float* __restrict__ W2, const float* __restrict__ b2,
    const float* __restrict__ W3, const float* __restrict__ b3,
    const float* __restrict__ b_scal,
    float* __restrict__ ypred, float* __restrict__ pairwise)
{
    extern __shared__ float smem[];
    float* W2s = smem;                          // 2 * KC * H_DIM
    float* h1s = smem + 2 * KC * H_DIM;         // H_DIM * K_NB
    float* red = h1s + H_DIM * K_NB;            // 8 * K_NB
    int*   cjs = (int*)(red + 8 * K_NB);        // K_NB

    const int tid  = threadIdx.x;
    const int i    = blockIdx.x;
    const int lane = tid & 31;
    const int warp = tid >> 5;

    if (tid < K_NB) cjs[tid] = nbrs[i * (K_NB + 1) + 1 + tid];

    // prefetch W2 tiles 0 and 1 (each 32 KB; 8 x 16B per thread)
    u32 w2s_base = (u32)__cvta_generic_to_shared(W2s);
    #pragma unroll
    for (int v = 0; v < 8; v++)
        cp_async16(w2s_base + (tid + v * 256) * 16,
                   W2 + (size_t)(tid + v * 256) * 4);
    cp_commit();
    #pragma unroll
    for (int v = 0; v < 8; v++)
        cp_async16(w2s_base + (KC * H_DIM) * 4 + (tid + v * 256) * 16,
                   W2 + (size_t)KC * H_DIM + (size_t)(tid + v * 256) * 4);
    cp_commit();

    __syncthreads();   // cjs visible

    // ---- layer 1 (transposed): warp w owns k in [w*32, w*32+32), lane owns j
    {
        const int cj = cjs[lane];
        const float4* Qv = (const float4*)(g_Q + (size_t)cj * H_DIM);
        const float4* Pv = (const float4*)(g_P + (size_t)i  * H_DIM);
        #pragma unroll
        for (int kk = 0; kk < KC; kk += 4) {
            int k  = warp * KC + kk;
            float4 q = Qv[k >> 2];
            float4 p = Pv[k >> 2];
            h1s[(k + 0) * K_NB + lane] = fmaxf(p.x + q.x, 0.f);
            h1s[(k + 1) * K_NB + lane] = fmaxf(p.y + q.y, 0.f);
            h1s[(k + 2) * K_NB + lane] = fmaxf(p.z + q.z, 0.f);
            h1s[(k + 3) * K_NB + lane] = fmaxf(p.w + q.w, 0.f);
        }
    }

    // ---- layer 2: acc over k-tiles, double-buffered weights
    u64 acc2[K_NB / 2];
    #pragma unroll
    for (int p = 0; p < K_NB / 2; p++) acc2[p] = 0ull;

    const ulonglong2* h1v = (const ulonglong2*)h1s;

    for (int tile = 0; tile < NTILES; tile++) {
        if (tile + 1 < NTILES) cp_wait<1>(); else cp_wait<0>();
        __syncthreads();   // tile data + (tile==0) h1 visible to all

        const float* wt = W2s + (tile & 1) * (KC * H_DIM);
        const int kbase = tile * KC;
        #pragma unroll 4
        for (int kk = 0; kk < KC; kk++) {
            u64 wp = pack2(wt[kk * H_DIM + tid]);
            const ulonglong2* row = h1v + (kbase + kk) * 8;
            #pragma unroll
            for (int q = 0; q < 8; q++) {
                ulonglong2 a = row[q];
                acc2[2 * q + 0] = ffma2(a.x, wp, acc2[2 * q + 0]);
                acc2[2 * q + 1] = ffma2(a.y, wp, acc2[2 * q + 1]);
            }
        }
        __syncthreads();   // everyone done with buffer before overwrite

        if (tile + 2 < NTILES) {
            int nt = tile + 2;
            u32 dst = w2s_base + (nt & 1) * (KC * H_DIM) * 4;
            const float* src = W2 + (size_t)nt * KC * H_DIM;
            #pragma unroll
            for (int v = 0; v < 8; v++)
                cp_async16(dst + (tid + v * 256) * 16,
                           src + (size_t)(tid + v * 256) * 4);
            cp_commit();
        }
    }

    float acc[K_NB];
    #pragma unroll
    for (int q = 0; q < 8; q++) {
        unpack2(acc2[2 * q + 0], acc[4 * q + 0], acc[4 * q + 1]);
        unpack2(acc2[2 * q + 1], acc[4 * q + 2], acc[4 * q + 3]);
    }

    // ---- layer 3 partial + block reduce
    {
        float b2t = b2[tid];
        float w3t = W3[tid];
        #pragma unroll
        for (int j = 0; j < K_NB; j++) {
            float v = fmaxf(acc[j] + b2t, 0.f) * w3t;
            #pragma unroll
            for (int o = 16; o > 0; o >>= 1)
                v += __shfl_xor_sync(0xffffffffu, v, o);
            if (lane == 0) red[warp * K_NB + j] = v;
        }
    }
    __syncthreads();

    if (warp == 0) {
        const int j = lane;
        float mlp = b3[0];
        #pragma unroll
        for (int w = 0; w < 8; w++) mlp += red[w * K_NB + j];

        float a = b_scal[0] * fabsf(mlp);
        float amax = a;
        #pragma unroll
        for (int o = 16; o > 0; o >>= 1)
            amax = fmaxf(amax, __shfl_xor_sync(0xffffffffu, amax, o));
        float e = __expf(a - amax);
        float esum = e;
        #pragma unroll
        for (int o = 16; o > 0; o >>= 1)
            esum += __shfl_xor_sync(0xffffffffu, esum, o);
        float wgt = mlp * (e / esum);

        int cj = cjs[j];
        float prop = t_arr[cj] - e_hat[cj];
        float yp = prop * wgt;
        #pragma unroll
        for (int o = 16; o > 0; o >>= 1)
            yp += __shfl_xor_sync(0xffffffffu, yp, o);
        if (lane == 0) ypred[i] = yp;

        // serial scatter (ascending j, last write wins)
        float* prow = pairwise + (size_t)i * N_NODES;
        #pragma unroll
        for (int jj = 0; jj < K_NB; jj++) {
            float wj = __shfl_sync(0xffffffffu, wgt, jj);
            int  cjj = __shfl_sync(0xffffffffu, cj,  jj);
            if (lane == 0) prow[cjj] = wj;
        }
        if (lane == 0) prow[i] = 0.f;
    }
}

// ---------------------------------------------------------------------------
extern "C" void kernel_launch(void* const* d_in, const int* in_sizes, int n_in,
                              void* d_out, int out_size) {
    const float* x     = (const float*)d_in[0];
    const int*   nbrs  = (const int*)  d_in[1];
    const float* t_arr = (const float*)d_in[2];
    const float* e_hat = (const float*)d_in[3];
    const float* W1    = (const float*)d_in[4];
    const float* b1    = (const float*)d_in[5];
    const float* W2    = (const float*)d_in[6];
    const float* b2    = (const float*)d_in[7];
    const float* W3    = (const float*)d_in[8];
    const float* b3    = (const float*)d_in[9];
    const float* bsc   = (const float*)d_in[10];

    float* ypred    = (float*)d_out;
    float* pairwise = ypred + N_NODES;

    static int smem_set = 0;
    if (!smem_set) {
        cudaFuncSetAttribute(mlp_kernel,
                             cudaFuncAttributeMaxDynamicSharedMemorySize,
                             SMEM_BYTES);
        smem_set = 1;
    }

    int n4 = out_size / 4;
    zero_kernel<<<8192, 256>>>((float4*)d_out, n4);
    pq_kernel<<<N_NODES / ROWS_PER_BLK, 256>>>(x, W1, b1);
    mlp_kernel<<<N_NODES, 256, SMEM_BYTES>>>(nbrs, t_arr, e_hat, W2, b2,
                                             W3, b3, bsc, ypred, pairwise);
}

// round 6
// speedup vs baseline: 3.0247x; 2.7407x over previous
#include <cuda_runtime.h>
#include <cuda_bf16.h>
#include <cstdint>
#include <stdint.h>
#include <math.h>

#define N_NODES 8192
#define K_NB    32
#define D_DIM   128
#define H_DIM   256
#define NPB     4          // nodes per block -> M = 128 rows

typedef unsigned int       u32;
typedef unsigned long long u64;

__device__ float g_P[N_NODES * H_DIM];   // x @ W1[:128] + b1
__device__ float g_Q[N_NODES * H_DIM];   // x @ W1[128:]
// W2^T bf16 hi/lo, 4 k-chunks, swizzled smem images ready for linear copy
__device__ __align__(16) unsigned char g_W2img[4][2][32768];

// ---------------- helpers ----------------
__device__ __forceinline__ u32 smem_u32(const void* p) {
    return (u32)__cvta_generic_to_shared(p);
}
__device__ __forceinline__ void cp_async16(u32 saddr, const void* gaddr) {
    asm volatile("cp.async.cg.shared.global [%0], [%1], 16;" :: "r"(saddr), "l"(gaddr));
}
__device__ __forceinline__ void cp_commit() { asm volatile("cp.async.commit_group;"); }
template <int N>
__device__ __forceinline__ void cp_wait() {
    asm volatile("cp.async.wait_group %0;" :: "n"(N) : "memory");
}
__device__ __forceinline__ void ldsm4(u32* r, u32 addr) {
    asm volatile("ldmatrix.sync.aligned.m8n8.x4.shared.b16 {%0,%1,%2,%3}, [%4];"
                 : "=r"(r[0]), "=r"(r[1]), "=r"(r[2]), "=r"(r[3]) : "r"(addr));
}
__device__ __forceinline__ void mma_bf16(float* c, const u32* a, const u32* b) {
    asm volatile(
        "mma.sync.aligned.m16n8k16.row.col.f32.bf16.bf16.f32 "
        "{%0,%1,%2,%3}, {%4,%5,%6,%7}, {%8,%9}, {%0,%1,%2,%3};"
        : "+f"(c[0]), "+f"(c[1]), "+f"(c[2]), "+f"(c[3])
        : "r"(a[0]), "r"(a[1]), "r"(a[2]), "r"(a[3]), "r"(b[0]), "r"(b[1]));
}
__device__ __forceinline__ u32 bf2pack(float lo_e, float hi_e) {
    __nv_bfloat162 t = __floats2bfloat162_rn(lo_e, hi_e);  // .x = lo_e (low half)
    return *(u32*)&t;
}

// ---------------------------------------------------------------------------
__global__ void zero_kernel(float4* __restrict__ out, int n4) {
    int stride = gridDim.x * blockDim.x;
    float4 z = make_float4(0.f, 0.f, 0.f, 0.f);
    for (int i = blockIdx.x * blockDim.x + threadIdx.x; i < n4; i += stride)
        out[i] = z;
}

// ---------------------------------------------------------------------------
#define ROWS_PER_BLK 16
__global__ __launch_bounds__(256) void pq_kernel(
    const float* __restrict__ x, const float* __restrict__ W1,
    const float* __restrict__ b1)
{
    __shared__ float xs[ROWS_PER_BLK * D_DIM];
    const int t = threadIdx.x;
    const int row0 = blockIdx.x * ROWS_PER_BLK;

    const float4* xsrc = (const float4*)(x + (size_t)row0 * D_DIM);
    float4* xdst = (float4*)xs;
    #pragma unroll
    for (int i = 0; i < (ROWS_PER_BLK * D_DIM / 4) / 256; i++)
        xdst[t + i * 256] = xsrc[t + i * 256];
    __syncthreads();

    float accP[ROWS_PER_BLK], accQ[ROWS_PER_BLK];
    #pragma unroll
    for (int r = 0; r < ROWS_PER_BLK; r++) { accP[r] = 0.f; accQ[r] = 0.f; }

    #pragma unroll 4
    for (int d = 0; d < D_DIM; d++) {
        float wp = W1[d * H_DIM + t];
        float wq = W1[(D_DIM + d) * H_DIM + t];
        #pragma unroll
        for (int r = 0; r < ROWS_PER_BLK; r++) {
            float xv = xs[r * D_DIM + d];
            accP[r] = fmaf(xv, wp, accP[r]);
            accQ[r] = fmaf(xv, wq, accQ[r]);
        }
    }
    float bb = b1[t];
    #pragma unroll
    for (int r = 0; r < ROWS_PER_BLK; r++) {
        g_P[(size_t)(row0 + r) * H_DIM + t] = accP[r] + bb;
        g_Q[(size_t)(row0 + r) * H_DIM + t] = accQ[r];
    }
}

// ---------------------------------------------------------------------------
// W2 -> per-chunk swizzled images of W2^T (bf16 hi/lo).
// image[ch][term]: rows n (0..255, 128B each), cols kk (0..63), 16B-chunk
// swizzle: off ^= (n&7)<<4.
// ---------------------------------------------------------------------------
__global__ void w2prep_kernel(const float* __restrict__ W2) {
    const int k = blockIdx.x;      // 0..255
    const int n = threadIdx.x;     // 0..255
    float v = W2[k * H_DIM + n];
    __nv_bfloat16 h = __float2bfloat16(v);
    __nv_bfloat16 l = __float2bfloat16(v - __bfloat162float(h));
    int ch = k >> 6, kk = k & 63;
    u32 off = (u32)(n * 128 + kk * 2) ^ (u32)((n & 7) << 4);
    *(__nv_bfloat16*)&g_W2img[ch][0][off] = h;
    *(__nv_bfloat16*)&g_W2img[ch][1][off] = l;
}

// ---------------------------------------------------------------------------
// Main kernel: 2048 blocks x 256 threads (8 warps), 4 nodes -> M=128.
// ---------------------------------------------------------------------------
#define W2S_BYTES 131072      // 2 buffers x (hi 32KB + lo 32KB)
#define H1_BYTES  32768       // hi 16KB + lo 16KB
#define SMEM_DYN  (W2S_BYTES + H1_BYTES)

__global__ __launch_bounds__(256, 1) void mlp_kernel(
    const int* __restrict__ nbrs,
    const float* __restrict__ t_arr, const float* __restrict__ e_hat,
    const float* __restrict__ b2, const float* __restrict__ W3,
    const float* __restrict__ b3, const float* __restrict__ b_scal,
    float* __restrict__ ypred, float* __restrict__ pairwise)
{
    extern __shared__ __align__(128) unsigned char dsm[];
    unsigned char* w2s_p  = dsm;                       // [buf][hi/lo]
    unsigned char* h1hi_p = dsm + W2S_BYTES;           // 16KB
    unsigned char* h1lo_p = dsm + W2S_BYTES + 16384;   // 16KB
    __shared__ float mlp_s[128];
    __shared__ int   cjs_s[128];
    __shared__ float b2s[H_DIM], w3s[H_DIM];

    const int tid  = threadIdx.x;
    const int lane = tid & 31;
    const int warp = tid >> 5;

    b2s[tid] = b2[tid];
    w3s[tid] = W3[tid];
    if (tid < 128)
        cjs_s[tid] = nbrs[(blockIdx.x * NPB + (tid >> 5)) * (K_NB + 1) + 1 + (tid & 31)];

    const u32 w2sa = smem_u32(w2s_p);

    // prefetch W2 chunks 0 and 1 (64KB each; 256B per thread)
    #pragma unroll
    for (int q = 0; q < 2; q++) {
        const unsigned char* sh = g_W2img[q][0];
        const unsigned char* sl = g_W2img[q][1];
        u32 dst = w2sa + q * 65536;
        #pragma unroll
        for (int t = 0; t < 8; t++) {
            int idx = (t * 256 + tid) * 16;
            cp_async16(dst + idx, sh + idx);
            cp_async16(dst + 32768 + idx, sl + idx);
        }
        cp_commit();
    }
    __syncthreads();   // cjs_s, b2s, w3s visible

    // h1 build assignment: thread -> row m = tid/2, half = tid&1 (32 k-values)
    const int  mrow = tid >> 1, half = tid & 1;
    const int  node_m = blockIdx.x * NPB + (mrow >> 5);
    const int  cjm = cjs_s[mrow];
    const float4* Qp = (const float4*)(g_Q + (size_t)cjm   * H_DIM) + half * 8;
    const float4* Pp = (const float4*)(g_P + (size_t)node_m * H_DIM) + half * 8;
    const u32 h1row = (u32)(mrow * 128);
    const u32 swm   = (u32)((mrow & 7) << 4);

    // MMA thread-geometry constants
    const int m_base = warp * 16;
    const int mA  = m_base + ((lane >> 3) & 1) * 8 + (lane & 7);
    const int kbA = (lane >> 4) * 8;
    const u32 aswz = (u32)((mA & 7) << 4);
    const int nB7  = (lane & 7) + ((lane >> 4) & 1) * 8;
    const int kkB7 = ((lane >> 3) & 1) * 8;
    const u32 bswz = (u32)((nB7 & 7) << 4);
    const u32 h1hi = smem_u32(h1hi_p);
    const u32 h1lo = smem_u32(h1lo_p);

    float cc[128];
    #pragma unroll
    for (int i = 0; i < 128; i++) cc[i] = 0.f;

    for (int ch = 0; ch < 4; ch++) {
        // ---- build h1 chunk ch (bf16 hi/lo, swizzled); own-warp rows only
        #pragma unroll
        for (int t2 = 0; t2 < 4; t2++) {
            float4 q0 = Qp[ch * 16 + t2 * 2];
            float4 q1 = Qp[ch * 16 + t2 * 2 + 1];
            float4 p0 = Pp[ch * 16 + t2 * 2];
            float4 p1 = Pp[ch * 16 + t2 * 2 + 1];
            float v0 = fmaxf(p0.x + q0.x, 0.f), v1 = fmaxf(p0.y + q0.y, 0.f);
            float v2 = fmaxf(p0.z + q0.z, 0.f), v3 = fmaxf(p0.w + q0.w, 0.f);
            float v4 = fmaxf(p1.x + q1.x, 0.f), v5 = fmaxf(p1.y + q1.y, 0.f);
            float v6 = fmaxf(p1.z + q1.z, 0.f), v7 = fmaxf(p1.w + q1.w, 0.f);
            float h0 = __bfloat162float(__float2bfloat16(v0));
            float h1v = __bfloat162float(__float2bfloat16(v1));
            float h2 = __bfloat162float(__float2bfloat16(v2));
            float h3 = __bfloat162float(__float2bfloat16(v3));
            float h4 = __bfloat162float(__float2bfloat16(v4));
            float h5 = __bfloat162float(__float2bfloat16(v5));
            float h6 = __bfloat162float(__float2bfloat16(v6));
            float h7 = __bfloat162float(__float2bfloat16(v7));
            uint4 hi4, lo4;
            hi4.x = bf2pack(h0, h1v); hi4.y = bf2pack(h2, h3);
            hi4.z = bf2pack(h4, h5);  hi4.w = bf2pack(h6, h7);
            lo4.x = bf2pack(v0 - h0, v1 - h1v); lo4.y = bf2pack(v2 - h2, v3 - h3);
            lo4.z = bf2pack(v4 - h4, v5 - h5);  lo4.w = bf2pack(v6 - h6, v7 - h7);
            u32 off = (h1row + (u32)((half * 4 + t2) * 16)) ^ swm;
            *(uint4*)(h1hi_p + off) = hi4;
            *(uint4*)(h1lo_p + off) = lo4;
        }

        if (ch < 3) cp_wait<1>(); else cp_wait<0>();
        __syncthreads();   // h1 chunk + W2 chunk visible

        // ---- MMAs for this chunk
        const u32 wbuf = w2sa + (u32)((ch & 1) * 65536);
        #pragma unroll
        for (int kt = 0; kt < 4; kt++) {
            u32 offA = (u32)(mA * 128 + (kt * 16 + kbA) * 2) ^ aswz;
            u32 ah[4], al[4];
            ldsm4(ah, h1hi + offA);
            ldsm4(al, h1lo + offA);
            #pragma unroll
            for (int np = 0; np < 16; np++) {
                u32 offB = (u32)(np * 2048 + nB7 * 128 + (kt * 16 + kkB7) * 2) ^ bswz;
                u32 bh[4], bl[4];
                ldsm4(bh, wbuf + offB);
                ldsm4(bl, wbuf + 32768 + offB);
                float* c0 = cc + (2 * np) * 4;
                float* c1 = cc + (2 * np + 1) * 4;
                mma_bf16(c0, ah, bh);
                mma_bf16(c0, al, bh);
                mma_bf16(c0, ah, bl);
                mma_bf16(c1, ah, bh + 2);
                mma_bf16(c1, al, bh + 2);
                mma_bf16(c1, ah, bl + 2);
            }
        }
        __syncthreads();   // all warps done with buffer (ch&1)

        if (ch + 2 < 4) {
            int q = ch + 2;
            const unsigned char* sh = g_W2img[q][0];
            const unsigned char* sl = g_W2img[q][1];
            u32 dst = w2sa + (u32)((ch & 1) * 65536);
            #pragma unroll
            for (int t = 0; t < 8; t++) {
                int idx = (t * 256 + tid) * 16;
                cp_async16(dst + idx, sh + idx);
                cp_async16(dst + 32768 + idx, sl + idx);
            }
            cp_commit();
        }
    }

    // ---- epilogue: rows m_base+g and m_base+8+g (g = lane>>2, tig = lane&3)
    {
        const int g = lane >> 2, tig = lane & 3;
        float acc0 = 0.f, acc1 = 0.f;
        #pragma unroll
        for (int nt = 0; nt < 32; nt++) {
            int col = nt * 8 + 2 * tig;
            float b0 = b2s[col], b1v = b2s[col + 1];
            float w0 = w3s[col], w1v = w3s[col + 1];
            acc0 = fmaf(fmaxf(cc[nt * 4 + 0] + b0, 0.f), w0, acc0);
            acc0 = fmaf(fmaxf(cc[nt * 4 + 1] + b1v, 0.f), w1v, acc0);
            acc1 = fmaf(fmaxf(cc[nt * 4 + 2] + b0, 0.f), w0, acc1);
            acc1 = fmaf(fmaxf(cc[nt * 4 + 3] + b1v, 0.f), w1v, acc1);
        }
        acc0 += __shfl_xor_sync(0xffffffffu, acc0, 1);
        acc0 += __shfl_xor_sync(0xffffffffu, acc0, 2);
        acc1 += __shfl_xor_sync(0xffffffffu, acc1, 1);
        acc1 += __shfl_xor_sync(0xffffffffu, acc1, 2);
        if (tig == 0) {
            float b3v = b3[0];
            mlp_s[m_base + g]     = acc0 + b3v;
            mlp_s[m_base + 8 + g] = acc1 + b3v;
        }
    }
    __syncthreads();

    // ---- softmax + outputs: warp w (0-3) handles node w
    if (warp < 4) {
        const int j = lane;
        const int node = blockIdx.x * NPB + warp;
        float mlp = mlp_s[warp * 32 + j];
        int cj = cjs_s[warp * 32 + j];

        float a = b_scal[0] * fabsf(mlp);
        float amax = a;
        #pragma unroll
        for (int o = 16; o > 0; o >>= 1)
            amax = fmaxf(amax, __shfl_xor_sync(0xffffffffu, amax, o));
        float e = __expf(a - amax);
        float esum = e;
        #pragma unroll
        for (int o = 16; o > 0; o >>= 1)
            esum += __shfl_xor_sync(0xffffffffu, esum, o);
        float wgt = mlp * (e / esum);

        float prop = t_arr[cj] - e_hat[cj];
        float yp = prop * wgt;
        #pragma unroll
        for (int o = 16; o > 0; o >>= 1)
            yp += __shfl_xor_sync(0xffffffffu, yp, o);
        if (lane == 0) ypred[node] = yp;

        // serial scatter (ascending j, last write wins)
        float* prow = pairwise + (size_t)node * N_NODES;
        #pragma unroll
        for (int jj = 0; jj < K_NB; jj++) {
            float wj = __shfl_sync(0xffffffffu, wgt, jj);
            int  cjj = __shfl_sync(0xffffffffu, cj,  jj);
            if (lane == 0) prow[cjj] = wj;
        }
        if (lane == 0) prow[node] = 0.f;
    }
}

// ---------------------------------------------------------------------------
extern "C" void kernel_launch(void* const* d_in, const int* in_sizes, int n_in,
                              void* d_out, int out_size) {
    const float* x     = (const float*)d_in[0];
    const int*   nbrs  = (const int*)  d_in[1];
    const float* t_arr = (const float*)d_in[2];
    const float* e_hat = (const float*)d_in[3];
    const float* W1    = (const float*)d_in[4];
    const float* b1    = (const float*)d_in[5];
    const float* W2    = (const float*)d_in[6];
    const float* b2    = (const float*)d_in[7];
    const float* W3    = (const float*)d_in[8];
    const float* b3    = (const float*)d_in[9];
    const float* bsc   = (const float*)d_in[10];

    float* ypred    = (float*)d_out;
    float* pairwise = ypred + N_NODES;

    static int smem_set = 0;
    if (!smem_set) {
        cudaFuncSetAttribute(mlp_kernel,
                             cudaFuncAttributeMaxDynamicSharedMemorySize,
                             SMEM_DYN);
        smem_set = 1;
    }

    int n4 = out_size / 4;
    zero_kernel<<<8192, 256>>>((float4*)d_out, n4);
    pq_kernel<<<N_NODES / ROWS_PER_BLK, 256>>>(x, W1, b1);
    w2prep_kernel<<<H_DIM, 256>>>(W2);
    mlp_kernel<<<N_NODES / NPB, 256, SMEM_DYN>>>(nbrs, t_arr, e_hat, b2, W3,
                                                 b3, bsc, ypred, pairwise);
}